// round 7
// baseline (speedup 1.0000x reference)
#include <cuda_runtime.h>

#define BSZ   64
#define SEQL  2048
#define HD    256
#define TTOT  (BSZ*SEQL)
#define LNEPS 1e-5f

__device__ float g_x [(size_t)TTOT*HD];
__device__ float g_h [(size_t)TTOT*HD];
__device__ float g_v [(size_t)TTOT*2*HD];   // scan buffer; first half doubles as MLP scratch
__device__ float g_Bstack[2*512*256];
__device__ float g_Beff  [2*256*512];
__device__ float g_W1t[2*256*256];
__device__ float g_W2t[2*256*256];
__device__ float g_abr[512], g_abi[512];
__device__ float g_cfr[512], g_cfi[512];
__device__ float g_sa[BSZ*HD], g_sb[BSZ*HD], g_sc[BSZ*HD];

__global__ void prep_coef(const float* __restrict__ lar, const float* __restrict__ aim,
                          const float* __restrict__ lstep){
    int n = threadIdx.x;
    #pragma unroll
    for (int i = 0; i < 2; i++){
        float st = expf(lstep[i]);
        float Ar = -expf(lar[i*256+n]);
        float Ai = aim[i*256+n];
        float mg = expf(Ar*st);
        float br = mg*cosf(Ai*st), bi = mg*sinf(Ai*st);
        g_abr[i*256+n] = br; g_abi[i*256+n] = bi;
        float nr = br - 1.0f, ni = bi;
        float den = Ar*Ar + Ai*Ai;
        g_cfr[i*256+n] = (nr*Ar + ni*Ai)/den;
        g_cfi[i*256+n] = (ni*Ar - nr*Ai)/den;
    }
}

__global__ void prep_bstack(const float* __restrict__ Bssm){
    int np = blockIdx.x, i = blockIdx.y, h = threadIdx.x;
    float c = (np < 256) ? g_cfr[i*256+h] : g_cfi[i*256+h];
    int n = np & 255;
    g_Bstack[((size_t)i*512 + np)*256 + h] = c * Bssm[((size_t)i*256 + n)*256 + h];
}

__global__ void prep_beff(const float* __restrict__ Cssm){
    int hrow = blockIdx.x, i = blockIdx.y, tid = threadIdx.x;
    for (int kk = tid; kk < 512; kk += 256){
        float v;
        if (kk < 256) v =  Cssm[(size_t)i*131072 + ((size_t)hrow*256 + kk)*2 + 0];
        else          v = -Cssm[(size_t)i*131072 + ((size_t)hrow*256 + (kk-256))*2 + 1];
        g_Beff[((size_t)i*256 + hrow)*512 + kk] = v;
    }
}

__global__ void prep_wt(const float* __restrict__ W1, const float* __restrict__ W2){
    int j = blockIdx.x, i = blockIdx.y, which = blockIdx.z, h = threadIdx.x;
    const float* W = which ? W2 : W1;
    float* O       = which ? g_W2t : g_W1t;
    O[((size_t)i*256 + j)*256 + h] = W[((size_t)i*256 + h)*256 + j];
}

__global__ void embed_kernel(const int* __restrict__ seqs, const float* __restrict__ emb,
                             const float* __restrict__ pos){
    size_t e = (size_t)blockIdx.x*256 + threadIdx.x;
    int t  = (int)(e >> 6);
    int hc = (int)(e & 63);
    int s  = t & (SEQL-1);
    int id = seqs[t];
    float4 o = make_float4(0.f,0.f,0.f,0.f);
    if (id != 0){
        float4 a = ((const float4*)emb)[(size_t)id*64 + hc];
        float4 p = ((const float4*)pos)[(size_t)s*64 + hc];
        o = make_float4(a.x+p.x, a.y+p.y, a.z+p.z, a.w+p.w);
    }
    ((float4*)g_x)[e] = o;
}

__global__ void ln_kernel(const float* __restrict__ gg, const float* __restrict__ bb){
    int lane = threadIdx.x & 31, w = threadIdx.x >> 5;
    size_t t = (size_t)blockIdx.x*8 + w;
    const float4* x4 = (const float4*)(g_x + t*HD);
    float4 v0 = x4[lane], v1 = x4[lane+32];
    float s = v0.x+v0.y+v0.z+v0.w + v1.x+v1.y+v1.z+v1.w;
    #pragma unroll
    for (int o=16;o;o>>=1) s += __shfl_xor_sync(0xffffffffu, s, o);
    float m = s * (1.0f/HD);
    float q = (v0.x-m)*(v0.x-m)+(v0.y-m)*(v0.y-m)+(v0.z-m)*(v0.z-m)+(v0.w-m)*(v0.w-m)
            + (v1.x-m)*(v1.x-m)+(v1.y-m)*(v1.y-m)+(v1.z-m)*(v1.z-m)+(v1.w-m)*(v1.w-m);
    #pragma unroll
    for (int o=16;o;o>>=1) q += __shfl_xor_sync(0xffffffffu, q, o);
    float var = q * (1.0f/HD);
    float r = rsqrtf(var + LNEPS);
    r = r * (1.5f - 0.5f*(var+LNEPS)*r*r);
    const float4* g4 = (const float4*)gg; const float4* b4 = (const float4*)bb;
    float4 G0=g4[lane], G1=g4[lane+32], B0=b4[lane], B1=b4[lane+32];
    float4 o0, o1;
    o0.x=(v0.x-m)*r*G0.x+B0.x; o0.y=(v0.y-m)*r*G0.y+B0.y; o0.z=(v0.z-m)*r*G0.z+B0.z; o0.w=(v0.w-m)*r*G0.w+B0.w;
    o1.x=(v1.x-m)*r*G1.x+B1.x; o1.y=(v1.y-m)*r*G1.y+B1.y; o1.z=(v1.z-m)*r*G1.z+B1.z; o1.w=(v1.w-m)*r*G1.w+B1.w;
    float4* h4 = (float4*)(g_h + t*HD);
    h4[lane]=o0; h4[lane+32]=o1;
}

// C[M,N] = A[M,K] * B[N,K]^T  (row-major, K contiguous)
// MODE 0: C = acc                  MODE 1: C += acc + aux1[c]*aux2[t,c]
// MODE 2: C = relu(acc+aux1[c])    MODE 3: C = (C + acc + aux1[c]) * mask(seqs[t])
template<int MODE>
__global__ __launch_bounds__(256)
void sgemm_kernel(const float* __restrict__ A, const float* __restrict__ B,
                  float* __restrict__ C, int K, int ldc,
                  const float* __restrict__ aux1, const float* __restrict__ aux2,
                  const int* __restrict__ seqs)
{
    __shared__ float As[2][16][128];
    __shared__ float Bs[2][16][128];
    const int tid = threadIdx.x;
    const int bm = blockIdx.y * 128;
    const int bn = blockIdx.x * 128;
    const int lr = tid >> 2;
    const int lc = (tid & 3) << 2;
    const float* Ag = A + (size_t)(bm + lr)*K + lc;
    const float* Bg = B + (size_t)(bn + lr)*K + lc;
    const size_t rstep = (size_t)64*K;

    float4 a0 = *(const float4*)Ag;
    float4 a1 = *(const float4*)(Ag + rstep);
    float4 b0 = *(const float4*)Bg;
    float4 b1 = *(const float4*)(Bg + rstep);
    As[0][lc+0][lr]=a0.x; As[0][lc+1][lr]=a0.y; As[0][lc+2][lr]=a0.z; As[0][lc+3][lr]=a0.w;
    As[0][lc+0][lr+64]=a1.x; As[0][lc+1][lr+64]=a1.y; As[0][lc+2][lr+64]=a1.z; As[0][lc+3][lr+64]=a1.w;
    Bs[0][lc+0][lr]=b0.x; Bs[0][lc+1][lr]=b0.y; Bs[0][lc+2][lr]=b0.z; Bs[0][lc+3][lr]=b0.w;
    Bs[0][lc+0][lr+64]=b1.x; Bs[0][lc+1][lr+64]=b1.y; Bs[0][lc+2][lr+64]=b1.z; Bs[0][lc+3][lr+64]=b1.w;
    __syncthreads();

    float acc[8][8];
    #pragma unroll
    for (int i=0;i<8;i++)
        #pragma unroll
        for (int j=0;j<8;j++) acc[i][j]=0.f;

    const int KT = K >> 4;
    const int ty4 = (tid >> 4) << 2;
    const int tx4 = (tid & 15) << 2;

    for (int kt = 0; kt < KT; kt++){
        const int cur = kt & 1;
        const bool pf = (kt+1) < KT;
        if (pf){
            const float* A2 = Ag + (kt+1)*16;
            const float* B2 = Bg + (kt+1)*16;
            a0 = *(const float4*)A2;
            a1 = *(const float4*)(A2 + rstep);
            b0 = *(const float4*)B2;
            b1 = *(const float4*)(B2 + rstep);
        }
        #pragma unroll
        for (int kk=0;kk<16;kk++){
            float4 ra0 = *(const float4*)&As[cur][kk][ty4];
            float4 ra1 = *(const float4*)&As[cur][kk][64+ty4];
            float4 rb0 = *(const float4*)&Bs[cur][kk][tx4];
            float4 rb1 = *(const float4*)&Bs[cur][kk][64+tx4];
            float a_[8] = {ra0.x,ra0.y,ra0.z,ra0.w, ra1.x,ra1.y,ra1.z,ra1.w};
            float b_[8] = {rb0.x,rb0.y,rb0.z,rb0.w, rb1.x,rb1.y,rb1.z,rb1.w};
            #pragma unroll
            for (int i=0;i<8;i++)
                #pragma unroll
                for (int j=0;j<8;j++)
                    acc[i][j] = fmaf(a_[i], b_[j], acc[i][j]);
        }
        if (pf){
            const int nx = cur ^ 1;
            As[nx][lc+0][lr]=a0.x; As[nx][lc+1][lr]=a0.y; As[nx][lc+2][lr]=a0.z; As[nx][lc+3][lr]=a0.w;
            As[nx][lc+0][lr+64]=a1.x; As[nx][lc+1][lr+64]=a1.y; As[nx][lc+2][lr+64]=a1.z; As[nx][lc+3][lr+64]=a1.w;
            Bs[nx][lc+0][lr]=b0.x; Bs[nx][lc+1][lr]=b0.y; Bs[nx][lc+2][lr]=b0.z; Bs[nx][lc+3][lr]=b0.w;
            Bs[nx][lc+0][lr+64]=b1.x; Bs[nx][lc+1][lr+64]=b1.y; Bs[nx][lc+2][lr+64]=b1.z; Bs[nx][lc+3][lr+64]=b1.w;
        }
        __syncthreads();
    }

    #pragma unroll
    for (int i=0;i<8;i++){
        const int mrow = bm + ((i<4) ? (ty4 + i) : (64 + ty4 + i - 4));
        const size_t t = (size_t)mrow;
        float4 v0 = make_float4(acc[i][0],acc[i][1],acc[i][2],acc[i][3]);
        float4 v1 = make_float4(acc[i][4],acc[i][5],acc[i][6],acc[i][7]);
        const int c0 = bn + tx4;
        const int c1 = bn + 64 + tx4;
        if (MODE == 0){
            *(float4*)&C[t*ldc + c0] = v0;
            *(float4*)&C[t*ldc + c1] = v1;
        } else if (MODE == 1){
            {
                float4 xv = *(float4*)&C[t*ldc + c0];
                float4 dv = *(const float4*)&aux1[c0];
                float4 hv = *(const float4*)&aux2[t*256 + c0];
                xv.x += v0.x + dv.x*hv.x; xv.y += v0.y + dv.y*hv.y;
                xv.z += v0.z + dv.z*hv.z; xv.w += v0.w + dv.w*hv.w;
                *(float4*)&C[t*ldc + c0] = xv;
            }
            {
                float4 xv = *(float4*)&C[t*ldc + c1];
                float4 dv = *(const float4*)&aux1[c1];
                float4 hv = *(const float4*)&aux2[t*256 + c1];
                xv.x += v1.x + dv.x*hv.x; xv.y += v1.y + dv.y*hv.y;
                xv.z += v1.z + dv.z*hv.z; xv.w += v1.w + dv.w*hv.w;
                *(float4*)&C[t*ldc + c1] = xv;
            }
        } else if (MODE == 2){
            {
                float4 bv = *(const float4*)&aux1[c0];
                float4 o; o.x=fmaxf(v0.x+bv.x,0.f); o.y=fmaxf(v0.y+bv.y,0.f);
                o.z=fmaxf(v0.z+bv.z,0.f); o.w=fmaxf(v0.w+bv.w,0.f);
                *(float4*)&C[t*ldc + c0] = o;
            }
            {
                float4 bv = *(const float4*)&aux1[c1];
                float4 o; o.x=fmaxf(v1.x+bv.x,0.f); o.y=fmaxf(v1.y+bv.y,0.f);
                o.z=fmaxf(v1.z+bv.z,0.f); o.w=fmaxf(v1.w+bv.w,0.f);
                *(float4*)&C[t*ldc + c1] = o;
            }
        } else {
            float msk = (seqs[t] != 0) ? 1.f : 0.f;
            {
                float4 xv = *(float4*)&C[t*ldc + c0];
                float4 bv = *(const float4*)&aux1[c0];
                xv.x=(xv.x+v0.x+bv.x)*msk; xv.y=(xv.y+v0.y+bv.y)*msk;
                xv.z=(xv.z+v0.z+bv.z)*msk; xv.w=(xv.w+v0.w+bv.w)*msk;
                *(float4*)&C[t*ldc + c0] = xv;
            }
            {
                float4 xv = *(float4*)&C[t*ldc + c1];
                float4 bv = *(const float4*)&aux1[c1];
                xv.x=(xv.x+v1.x+bv.x)*msk; xv.y=(xv.y+v1.y+bv.y)*msk;
                xv.z=(xv.z+v1.z+bv.z)*msk; xv.w=(xv.w+v1.w+bv.w)*msk;
                *(float4*)&C[t*ldc + c1] = xv;
            }
        }
    }
}

__global__ void scan_kernel(int blk){
    int b = blockIdx.x, n = threadIdx.x;
    float ar = g_abr[blk*256+n], ai = g_abi[blk*256+n];
    size_t base = (size_t)b*SEQL*512 + n;
    float xr = 0.f, xi = 0.f;
    const int CH = 16;
    float vr[2][CH], vi[2][CH];
    #pragma unroll
    for (int k=0;k<CH;k++){ vr[0][k]=g_v[base + (size_t)k*512]; vi[0][k]=g_v[base + (size_t)k*512 + 256]; }
    int cb = 0;
    for (int c=0;c<SEQL/CH;c++){
        int nb = cb ^ 1;
        if (c+1 < SEQL/CH){
            size_t b2 = base + (size_t)(c+1)*CH*512;
            #pragma unroll
            for (int k=0;k<CH;k++){ vr[nb][k]=g_v[b2 + (size_t)k*512]; vi[nb][k]=g_v[b2 + (size_t)k*512 + 256]; }
        }
        size_t b1 = base + (size_t)c*CH*512;
        #pragma unroll
        for (int k=0;k<CH;k++){
            float nxr = fmaf(ar, xr, fmaf(-ai, xi, vr[cb][k]));
            float nxi = fmaf(ar, xi, fmaf( ai, xr, vi[cb][k]));
            xr = nxr; xi = nxi;
            g_v[b1 + (size_t)k*512]       = xr;
            g_v[b1 + (size_t)k*512 + 256] = xi;
        }
        cb = nb;
    }
}

__global__ void fk_y1(const float* __restrict__ Beff1, const float* __restrict__ D1){
    int b = blockIdx.x, h = threadIdx.x;
    __shared__ float sx[512];
    size_t t = (size_t)b*SEQL + (SEQL-1);
    sx[h]     = g_v[t*512 + h];
    sx[h+256] = g_v[t*512 + 256 + h];
    __syncthreads();
    float acc = 0.f;
    #pragma unroll 8
    for (int k=0;k<512;k++) acc = fmaf(sx[k], Beff1[(size_t)h*512 + k], acc);
    g_x[t*HD + h] += acc + D1[h]*g_h[t*HD + h];
}

__device__ __forceinline__ float blk_sum256(float v){
    __shared__ float sm[8];
    int lane = threadIdx.x & 31, w = threadIdx.x >> 5;
    #pragma unroll
    for (int o=16;o;o>>=1) v += __shfl_xor_sync(0xffffffffu, v, o);
    if (lane == 0) sm[w] = v;
    __syncthreads();
    float r = (threadIdx.x < 8) ? sm[threadIdx.x] : 0.f;
    if (threadIdx.x < 32){
        #pragma unroll
        for (int o=4;o;o>>=1) r += __shfl_xor_sync(0xffffffffu, r, o);
    }
    if (threadIdx.x == 0) sm[0] = r;
    __syncthreads();
    float out = sm[0];
    __syncthreads();
    return out;
}

__global__ void fk_ln_last(const float* __restrict__ gg, const float* __restrict__ bb){
    int b = blockIdx.x, j = threadIdx.x;
    size_t t = (size_t)b*SEQL + (SEQL-1);
    float x = g_x[t*HD + j];
    float m = blk_sum256(x) * (1.0f/HD);
    float d = x - m;
    float var = blk_sum256(d*d) * (1.0f/HD);
    float r = rsqrtf(var + LNEPS);
    r = r * (1.5f - 0.5f*(var+LNEPS)*r*r);
    g_sa[b*HD + j] = d*r*gg[j] + bb[j];
}

__global__ void fk_mlp1(const float* __restrict__ W1b, const float* __restrict__ b1b){
    int b = blockIdx.x, j = threadIdx.x;
    __shared__ float sh[HD];
    sh[j] = g_sa[b*HD + j];
    __syncthreads();
    float acc = 0.f;
    #pragma unroll 8
    for (int h=0;h<HD;h++) acc = fmaf(sh[h], W1b[(size_t)h*HD + j], acc);
    g_sb[b*HD + j] = fmaxf(acc + b1b[j], 0.f);
}

__global__ void fk_mlp2_lnf(const float* __restrict__ W2b, const float* __restrict__ b2b,
                            const int* __restrict__ seqs,
                            const float* __restrict__ lfg, const float* __restrict__ lfb){
    int b = blockIdx.x, j = threadIdx.x;
    __shared__ float sh[HD];
    sh[j] = g_sb[b*HD + j];
    __syncthreads();
    float acc = 0.f;
    #pragma unroll 8
    for (int h=0;h<HD;h++) acc = fmaf(sh[h], W2b[(size_t)h*HD + j], acc);
    size_t t = (size_t)b*SEQL + (SEQL-1);
    float xv = g_x[t*HD + j] + acc + b2b[j];
    if (seqs[t] == 0) xv = 0.f;
    float m = blk_sum256(xv) * (1.0f/HD);
    float d = xv - m;
    float var = blk_sum256(d*d) * (1.0f/HD);
    float r = rsqrtf(var + LNEPS);
    r = r * (1.5f - 0.5f*(var+LNEPS)*r*r);
    g_sc[b*HD + j] = d*r*lfg[j] + lfb[j];
}

__global__ void fk_logits(const int* __restrict__ idxs, const float* __restrict__ emb,
                          float* __restrict__ out){
    int b = blockIdx.x, tid = threadIdx.x;
    int w = tid >> 5, lane = tid & 31;
    __shared__ __align__(16) float sh[HD];
    sh[tid] = g_sc[b*HD + tid];
    __syncthreads();
    const float4* sh4 = (const float4*)sh;
    float4 s0 = sh4[lane], s1 = sh4[lane+32];
    for (int c = w; c < 101; c += 8){
        int id = idxs[b*101 + c];
        const float4* e4 = (const float4*)(emb + (size_t)id*HD);
        float4 a0 = e4[lane], a1 = e4[lane+32];
        float p = a0.x*s0.x + a0.y*s0.y + a0.z*s0.z + a0.w*s0.w
                + a1.x*s1.x + a1.y*s1.y + a1.z*s1.z + a1.w*s1.w;
        #pragma unroll
        for (int o=16;o;o>>=1) p += __shfl_xor_sync(0xffffffffu, p, o);
        if (lane == 0) out[b*101 + c] = p;
    }
}

extern "C" void kernel_launch(void* const* d_in, const int* in_sizes, int n_in,
                              void* d_out, int out_size){
    const int*   seqs = (const int*)  d_in[0];
    const int*   idxs = (const int*)  d_in[1];
    const float* emb  = (const float*)d_in[2];
    const float* pos  = (const float*)d_in[3];
    const float* ln_g = (const float*)d_in[4];
    const float* ln_b = (const float*)d_in[5];
    const float* lar  = (const float*)d_in[6];
    const float* aim  = (const float*)d_in[7];
    const float* Bssm = (const float*)d_in[8];
    const float* Cssm = (const float*)d_in[9];
    const float* Dssm = (const float*)d_in[10];
    const float* lstep= (const float*)d_in[11];
    const float* W1   = (const float*)d_in[12];
    const float* b1   = (const float*)d_in[13];
    const float* W2   = (const float*)d_in[14];
    const float* b2   = (const float*)d_in[15];
    const float* lfg  = (const float*)d_in[16];
    const float* lfb  = (const float*)d_in[17];
    float* out = (float*)d_out;

    float *p_x, *p_h, *p_v, *p_Bst, *p_Bef, *p_W1t, *p_W2t;
    cudaGetSymbolAddress((void**)&p_x,  g_x);
    cudaGetSymbolAddress((void**)&p_h,  g_h);
    cudaGetSymbolAddress((void**)&p_v,  g_v);
    cudaGetSymbolAddress((void**)&p_Bst,g_Bstack);
    cudaGetSymbolAddress((void**)&p_Bef,g_Beff);
    cudaGetSymbolAddress((void**)&p_W1t,g_W1t);
    cudaGetSymbolAddress((void**)&p_W2t,g_W2t);
    float* p_t = p_v;   // MLP scratch aliases the (dead-between-uses) scan buffer

    prep_coef  <<<1, 256>>>(lar, aim, lstep);
    prep_bstack<<<dim3(512,2), 256>>>(Bssm);
    prep_beff  <<<dim3(256,2), 256>>>(Cssm);
    prep_wt    <<<dim3(256,2,2), 256>>>(W1, W2);

    embed_kernel<<<TTOT/4, 256>>>(seqs, emb, pos);

    const dim3 gV(4, TTOT/128), gY(2, TTOT/128), gM(2, TTOT/128);

    // ---- block 0 ----
    ln_kernel<<<TTOT/8, 256>>>(ln_g, ln_b);
    sgemm_kernel<0><<<gV, 256>>>(p_h, p_Bst, p_v, 256, 512, nullptr, nullptr, nullptr);
    scan_kernel<<<BSZ, 256>>>(0);
    sgemm_kernel<1><<<gY, 256>>>(p_v, p_Bef, p_x, 512, 256, Dssm, p_h, nullptr);
    ln_kernel<<<TTOT/8, 256>>>(ln_g, ln_b);
    sgemm_kernel<2><<<gM, 256>>>(p_h, p_W1t, p_t, 256, 256, b1, nullptr, nullptr);
    sgemm_kernel<3><<<gM, 256>>>(p_t, p_W2t, p_x, 256, 256, b2, nullptr, seqs);

    // ---- block 1 ----
    ln_kernel<<<TTOT/8, 256>>>(ln_g + HD, ln_b + HD);
    sgemm_kernel<0><<<gV, 256>>>(p_h, p_Bst + 512*256, p_v, 256, 512, nullptr, nullptr, nullptr);
    scan_kernel<<<BSZ, 256>>>(1);
    fk_y1<<<BSZ, 256>>>(p_Bef + 256*512, Dssm + HD);

    // ---- last-token tail ----
    fk_ln_last<<<BSZ, 256>>>(ln_g + HD, ln_b + HD);
    fk_mlp1<<<BSZ, 256>>>(W1 + 65536, b1 + HD);
    fk_mlp2_lnf<<<BSZ, 256>>>(W2 + 65536, b2 + HD, seqs, lfg, lfb);
    fk_logits<<<BSZ, 256>>>(idxs, emb, out);
}

// round 14
// speedup vs baseline: 1.4676x; 1.4676x over previous
#include <cuda_runtime.h>
#include <cuda_bf16.h>
#include <cstdint>

#define BSZ   64
#define SEQL  2048
#define HD    256
#define TTOT  (BSZ*SEQL)
#define LNEPS 1e-5f

// ---------------- scratch ----------------
__device__ float g_x [(size_t)TTOT*HD];
__device__ float g_h [(size_t)TTOT*HD];
__device__ float g_v [(size_t)TTOT*2*HD];   // scan buffer; also hosts MLP hi/lo (aliased, disjoint lifetime)
__device__ __nv_bfloat16 g_ahi[(size_t)TTOT*512];
__device__ __nv_bfloat16 g_alo[(size_t)TTOT*512];
__device__ float g_Bstack[2*512*256];
__device__ float g_Beff  [2*256*512];
__device__ float g_W1t[2*256*256];
__device__ float g_W2t[2*256*256];
__device__ __nv_bfloat16 g_bst_h[2*512*256], g_bst_l[2*512*256];
__device__ __nv_bfloat16 g_bef_h[2*256*512], g_bef_l[2*256*512];
__device__ __nv_bfloat16 g_w1_h[2*256*256],  g_w1_l[2*256*256];
__device__ __nv_bfloat16 g_w2_h[2*256*256],  g_w2_l[2*256*256];
__device__ float g_abr[512], g_abi[512];
__device__ float g_cfr[512], g_cfi[512];
__device__ float g_sa[BSZ*HD], g_sb[BSZ*HD], g_sc[BSZ*HD];

// ---------------- baseline-ISA tensor helpers (sm_80+ features only) ----------------
__device__ __forceinline__ uint32_t smem_u32(const void* p){
    uint32_t a;
    asm("{ .reg .u64 t; cvta.to.shared.u64 t, %1; cvt.u32.u64 %0, t; }" : "=r"(a) : "l"(p));
    return a;
}
__device__ __forceinline__ void cpa16(uint32_t s, const void* g){
    asm volatile("cp.async.cg.shared.global [%0], [%1], 16;" :: "r"(s), "l"(g));
}
__device__ __forceinline__ void ldmx4(uint32_t* r, uint32_t a){
    asm volatile("ldmatrix.sync.aligned.m8n8.x4.shared.b16 {%0,%1,%2,%3}, [%4];"
        : "=r"(r[0]),"=r"(r[1]),"=r"(r[2]),"=r"(r[3]) : "r"(a));
}
__device__ __forceinline__ void ldmx2(uint32_t* r, uint32_t a){
    asm volatile("ldmatrix.sync.aligned.m8n8.x2.shared.b16 {%0,%1}, [%2];"
        : "=r"(r[0]),"=r"(r[1]) : "r"(a));
}
__device__ __forceinline__ void mma16816(float* c, const uint32_t* a, const uint32_t* b){
    asm volatile("mma.sync.aligned.m16n8k16.row.col.f32.bf16.bf16.f32 "
        "{%0,%1,%2,%3}, {%4,%5,%6,%7}, {%8,%9}, {%0,%1,%2,%3};"
        : "+f"(c[0]),"+f"(c[1]),"+f"(c[2]),"+f"(c[3])
        : "r"(a[0]),"r"(a[1]),"r"(a[2]),"r"(a[3]), "r"(b[0]),"r"(b[1]));
}

// ---------------- prep ----------------
__global__ void prep_coef(const float* __restrict__ lar, const float* __restrict__ aim,
                          const float* __restrict__ lstep){
    int n = threadIdx.x;
    #pragma unroll
    for (int i = 0; i < 2; i++){
        float st = expf(lstep[i]);
        float Ar = -expf(lar[i*256+n]);
        float Ai = aim[i*256+n];
        float mg = expf(Ar*st);
        float br = mg*cosf(Ai*st), bi = mg*sinf(Ai*st);
        g_abr[i*256+n] = br; g_abi[i*256+n] = bi;
        float nr = br - 1.0f, ni = bi;
        float den = Ar*Ar + Ai*Ai;
        g_cfr[i*256+n] = (nr*Ar + ni*Ai)/den;
        g_cfi[i*256+n] = (ni*Ar - nr*Ai)/den;
    }
}
__global__ void prep_bstack(const float* __restrict__ Bssm){
    int np = blockIdx.x, i = blockIdx.y, h = threadIdx.x;
    float c = (np < 256) ? g_cfr[i*256+h] : g_cfi[i*256+h];
    int n = np & 255;
    g_Bstack[((size_t)i*512 + np)*256 + h] = c * Bssm[((size_t)i*256 + n)*256 + h];
}
__global__ void prep_beff(const float* __restrict__ Cssm){
    int hrow = blockIdx.x, i = blockIdx.y, tid = threadIdx.x;
    for (int kk = tid; kk < 512; kk += 256){
        float v;
        if (kk < 256) v =  Cssm[(size_t)i*131072 + ((size_t)hrow*256 + kk)*2 + 0];
        else          v = -Cssm[(size_t)i*131072 + ((size_t)hrow*256 + (kk-256))*2 + 1];
        g_Beff[((size_t)i*256 + hrow)*512 + kk] = v;
    }
}
__global__ void prep_wt(const float* __restrict__ W1, const float* __restrict__ W2){
    int j = blockIdx.x, i = blockIdx.y, which = blockIdx.z, h = threadIdx.x;
    const float* W = which ? W2 : W1;
    float* O       = which ? g_W2t : g_W1t;
    O[((size_t)i*256 + j)*256 + h] = W[((size_t)i*256 + h)*256 + j];
}
__global__ void split_f32(const float* __restrict__ src, __nv_bfloat16* __restrict__ hi,
                          __nv_bfloat16* __restrict__ lo){
    size_t i4 = (size_t)blockIdx.x*256 + threadIdx.x;
    float4 v = ((const float4*)src)[i4];
    __nv_bfloat16 h0=__float2bfloat16_rn(v.x), h1=__float2bfloat16_rn(v.y),
                  h2=__float2bfloat16_rn(v.z), h3=__float2bfloat16_rn(v.w);
    __nv_bfloat16 l0=__float2bfloat16_rn(v.x-__bfloat162float(h0)),
                  l1=__float2bfloat16_rn(v.y-__bfloat162float(h1)),
                  l2=__float2bfloat16_rn(v.z-__bfloat162float(h2)),
                  l3=__float2bfloat16_rn(v.w-__bfloat162float(h3));
    __nv_bfloat162* H = (__nv_bfloat162*)(hi + i4*4);
    __nv_bfloat162* L = (__nv_bfloat162*)(lo + i4*4);
    H[0] = __nv_bfloat162(h0,h1); H[1] = __nv_bfloat162(h2,h3);
    L[0] = __nv_bfloat162(l0,l1); L[1] = __nv_bfloat162(l2,l3);
}

__global__ void embed_kernel(const int* __restrict__ seqs, const float* __restrict__ emb,
                             const float* __restrict__ pos){
    size_t e = (size_t)blockIdx.x*256 + threadIdx.x;
    int t  = (int)(e >> 6);
    int hc = (int)(e & 63);
    int s  = t & (SEQL-1);
    int id = seqs[t];
    float4 o = make_float4(0.f,0.f,0.f,0.f);
    if (id != 0){
        float4 a = ((const float4*)emb)[(size_t)id*64 + hc];
        float4 p = ((const float4*)pos)[(size_t)s*64 + hc];
        o = make_float4(a.x+p.x, a.y+p.y, a.z+p.z, a.w+p.w);
    }
    ((float4*)g_x)[e] = o;
}

__device__ __forceinline__ void st4bf(__nv_bfloat16* p, float a, float b, float c, float d,
                                      __nv_bfloat16* pl){
    __nv_bfloat16 h0=__float2bfloat16_rn(a), h1=__float2bfloat16_rn(b),
                  h2=__float2bfloat16_rn(c), h3=__float2bfloat16_rn(d);
    ((__nv_bfloat162*)p)[0] = __nv_bfloat162(h0,h1);
    ((__nv_bfloat162*)p)[1] = __nv_bfloat162(h2,h3);
    __nv_bfloat16 l0=__float2bfloat16_rn(a-__bfloat162float(h0)),
                  l1=__float2bfloat16_rn(b-__bfloat162float(h1)),
                  l2=__float2bfloat16_rn(c-__bfloat162float(h2)),
                  l3=__float2bfloat16_rn(d-__bfloat162float(h3));
    ((__nv_bfloat162*)pl)[0] = __nv_bfloat162(l0,l1);
    ((__nv_bfloat162*)pl)[1] = __nv_bfloat162(l2,l3);
}
__device__ __forceinline__ void st2bf(__nv_bfloat16* ph, __nv_bfloat16* pl, float a, float b){
    __nv_bfloat16 h0=__float2bfloat16_rn(a), h1=__float2bfloat16_rn(b);
    *(__nv_bfloat162*)ph = __nv_bfloat162(h0,h1);
    __nv_bfloat16 l0=__float2bfloat16_rn(a-__bfloat162float(h0)),
                  l1=__float2bfloat16_rn(b-__bfloat162float(h1));
    *(__nv_bfloat162*)pl = __nv_bfloat162(l0,l1);
}

__global__ void ln_split(const float* __restrict__ gg, const float* __restrict__ bb){
    int lane = threadIdx.x & 31, w = threadIdx.x >> 5;
    size_t t = (size_t)blockIdx.x*8 + w;
    const float4* x4 = (const float4*)(g_x + t*HD);
    float4 v0 = x4[lane], v1 = x4[lane+32];
    float s = v0.x+v0.y+v0.z+v0.w + v1.x+v1.y+v1.z+v1.w;
    #pragma unroll
    for (int o=16;o;o>>=1) s += __shfl_xor_sync(0xffffffffu, s, o);
    float m = s * (1.0f/HD);
    float q = (v0.x-m)*(v0.x-m)+(v0.y-m)*(v0.y-m)+(v0.z-m)*(v0.z-m)+(v0.w-m)*(v0.w-m)
            + (v1.x-m)*(v1.x-m)+(v1.y-m)*(v1.y-m)+(v1.z-m)*(v1.z-m)+(v1.w-m)*(v1.w-m);
    #pragma unroll
    for (int o=16;o;o>>=1) q += __shfl_xor_sync(0xffffffffu, q, o);
    float var = q * (1.0f/HD);
    float r = rsqrtf(var + LNEPS);
    r = r * (1.5f - 0.5f*(var+LNEPS)*r*r);
    const float4* g4 = (const float4*)gg; const float4* b4 = (const float4*)bb;
    float4 G0=g4[lane], G1=g4[lane+32], B0=b4[lane], B1=b4[lane+32];
    float4 o0, o1;
    o0.x=(v0.x-m)*r*G0.x+B0.x; o0.y=(v0.y-m)*r*G0.y+B0.y; o0.z=(v0.z-m)*r*G0.z+B0.z; o0.w=(v0.w-m)*r*G0.w+B0.w;
    o1.x=(v1.x-m)*r*G1.x+B1.x; o1.y=(v1.y-m)*r*G1.y+B1.y; o1.z=(v1.z-m)*r*G1.z+B1.z; o1.w=(v1.w-m)*r*G1.w+B1.w;
    float4* h4 = (float4*)(g_h + t*HD);
    h4[lane]=o0; h4[lane+32]=o1;
    st4bf(g_ahi + t*256 + lane*4,      o0.x,o0.y,o0.z,o0.w, g_alo + t*256 + lane*4);
    st4bf(g_ahi + t*256 + 128+lane*4,  o1.x,o1.y,o1.z,o1.w, g_alo + t*256 + 128+lane*4);
}

// ---------------- mma.sync GEMM: C[M,N]=A[M,K]*B[N,K]^T, bf16 3-split, f32 accum ----------------
// CTA tile 128x128, 8 warps (4m x 2n), K chunks of 64, cp.async double buffer.
#define RS   144                  // padded smem row stride bytes (64 bf16 + 8 pad)
#define ARR  (128*RS)             // 18432 bytes per array
#define CHUNKB (4*ARR)            // Ah,Al,Bh,Bl
#define GSMEM  (2*CHUNKB)         // 147456

template<int MODE>
__global__ void __launch_bounds__(256,1) tcg(
    const __nv_bfloat16* __restrict__ Ahi, const __nv_bfloat16* __restrict__ Alo,
    const __nv_bfloat16* __restrict__ Bhi, const __nv_bfloat16* __restrict__ Blo,
    float* __restrict__ C, int K, int ldc,
    const float* __restrict__ aux1, const float* __restrict__ aux2,
    const int* __restrict__ seqs,
    __nv_bfloat16* __restrict__ ohi, __nv_bfloat16* __restrict__ olo)
{
    extern __shared__ __align__(16) char smem[];
    const uint32_t sbase = smem_u32(smem);
    const int tid = threadIdx.x;
    const int lane = tid & 31, wid = tid >> 5;
    const int wm = wid & 3, wn = wid >> 2;
    const size_t bm = (size_t)blockIdx.y * 128;
    const size_t bn = (size_t)blockIdx.x * 128;
    const int nch = K >> 6;

    auto issue = [&](int c, int s){
        const uint32_t sb = sbase + s*CHUNKB;
        const __nv_bfloat16* srcs[4] = {Ahi, Alo, Bhi, Blo};
        const size_t rb[4] = {bm, bm, bn, bn};
        #pragma unroll
        for (int a = 0; a < 4; a++){
            const uint32_t sa = sb + a*ARR;
            const __nv_bfloat16* src = srcs[a];
            #pragma unroll
            for (int it = 0; it < 4; it++){
                int idx = tid + it*256;
                int row = idx >> 3, seg = idx & 7;
                const char* g = (const char*)(src + (rb[a]+row)*(size_t)K + c*64) + seg*16;
                cpa16(sa + row*RS + seg*16, g);
            }
        }
        asm volatile("cp.async.commit_group;" ::: "memory");
    };

    float acc[2][8][4];
    #pragma unroll
    for (int i=0;i<2;i++)
        #pragma unroll
        for (int j=0;j<8;j++)
            #pragma unroll
            for (int k=0;k<4;k++) acc[i][j][k]=0.f;

    issue(0, 0);

    for (int c = 0; c < nch; c++){
        const int s = c & 1;
        if (c+1 < nch){
            issue(c+1, s^1);
            asm volatile("cp.async.wait_group 1;" ::: "memory");
        } else {
            asm volatile("cp.async.wait_group 0;" ::: "memory");
        }
        __syncthreads();
        const uint32_t aH = sbase + s*CHUNKB;
        const uint32_t aL = aH + ARR;
        const uint32_t bH = aH + 2*ARR;
        const uint32_t bL = aH + 3*ARR;
        #pragma unroll
        for (int ks = 0; ks < 4; ks++){
            uint32_t fAH[2][4], fAL[2][4];
            {
                const int tile = lane >> 3, r = lane & 7;
                const int arow0 = wm*32 + (tile&1)*8 + r;
                const int ko = ks*16 + (tile>>1)*8;
                #pragma unroll
                for (int tm = 0; tm < 2; tm++){
                    const uint32_t off = (uint32_t)(arow0 + tm*16)*RS + ko*2;
                    ldmx4(fAH[tm], aH + off);
                    ldmx4(fAL[tm], aL + off);
                }
            }
            uint32_t fBH[8][2], fBL[8][2];
            {
                const int l15 = lane & 15;
                const int tile = l15 >> 3, r = l15 & 7;
                const int ko = ks*16 + tile*8;
                #pragma unroll
                for (int nt = 0; nt < 8; nt++){
                    const uint32_t off = (uint32_t)(wn*64 + nt*8 + r)*RS + ko*2;
                    ldmx2(fBH[nt], bH + off);
                    ldmx2(fBL[nt], bL + off);
                }
            }
            #pragma unroll
            for (int tm = 0; tm < 2; tm++)
                #pragma unroll
                for (int nt = 0; nt < 8; nt++){
                    mma16816(acc[tm][nt], fAH[tm], fBH[nt]);
                    mma16816(acc[tm][nt], fAH[tm], fBL[nt]);
                    mma16816(acc[tm][nt], fAL[tm], fBH[nt]);
                }
        }
        __syncthreads();
    }

    // epilogue
    const int g = lane >> 2, t2 = (lane & 3)*2;
    #pragma unroll
    for (int tm = 0; tm < 2; tm++){
        #pragma unroll
        for (int nt = 0; nt < 8; nt++){
            const size_t col = bn + wn*64 + nt*8 + t2;
            #pragma unroll
            for (int half = 0; half < 2; half++){
                const size_t row = bm + wm*32 + tm*16 + g + half*8;
                const float a0 = acc[tm][nt][half*2+0];
                const float a1 = acc[tm][nt][half*2+1];
                if (MODE == 0){
                    *(float2*)&C[row*(size_t)ldc + col] = make_float2(a0, a1);
                } else if (MODE == 1){
                    float2 xv = *(float2*)&C[row*(size_t)ldc + col];
                    float2 dv = *(const float2*)&aux1[col];
                    float2 hv = *(const float2*)&aux2[row*256 + col];
                    xv.x += a0 + dv.x*hv.x; xv.y += a1 + dv.y*hv.y;
                    *(float2*)&C[row*(size_t)ldc + col] = xv;
                } else if (MODE == 2){
                    float2 bv = *(const float2*)&aux1[col];
                    st2bf(ohi + row*256 + col, olo + row*256 + col,
                          fmaxf(a0+bv.x, 0.f), fmaxf(a1+bv.y, 0.f));
                } else {
                    float msk = (seqs[row] != 0) ? 1.f : 0.f;
                    float2 xv = *(float2*)&C[row*(size_t)ldc + col];
                    float2 bv = *(const float2*)&aux1[col];
                    xv.x = (xv.x + a0 + bv.x)*msk;
                    xv.y = (xv.y + a1 + bv.y)*msk;
                    *(float2*)&C[row*(size_t)ldc + col] = xv;
                }
            }
        }
    }
}

// ---------------- scan ----------------
__global__ void scan_kernel(int blk){
    int b = blockIdx.x;
    int n = blockIdx.y*64 + threadIdx.x;
    float ar = g_abr[blk*256+n], ai = g_abi[blk*256+n];
    size_t base = (size_t)b*SEQL*512 + n;
    float xr = 0.f, xi = 0.f;
    const int CH = 16;
    float vr[2][CH], vi[2][CH];
    #pragma unroll
    for (int k=0;k<CH;k++){ vr[0][k]=g_v[base + (size_t)k*512]; vi[0][k]=g_v[base + (size_t)k*512 + 256]; }
    int cb = 0;
    for (int c=0;c<SEQL/CH;c++){
        int nb = cb ^ 1;
        if (c+1 < SEQL/CH){
            size_t b2 = base + (size_t)(c+1)*CH*512;
            #pragma unroll
            for (int k=0;k<CH;k++){ vr[nb][k]=g_v[b2 + (size_t)k*512]; vi[nb][k]=g_v[b2 + (size_t)k*512 + 256]; }
        }
        size_t b1 = base + (size_t)c*CH*512;
        #pragma unroll
        for (int k=0;k<CH;k++){
            float nxr = fmaf(ar, xr, fmaf(-ai, xi, vr[cb][k]));
            float nxi = fmaf(ar, xi, fmaf( ai, xr, vi[cb][k]));
            xr = nxr; xi = nxi;
            g_v[b1 + (size_t)k*512]       = xr;
            g_v[b1 + (size_t)k*512 + 256] = xi;
        }
        cb = nb;
    }
}

// ---------------- last-token tail ----------------
__global__ void fk_y1(const float* __restrict__ Beff1, const float* __restrict__ D1){
    int b = blockIdx.x, h = threadIdx.x;
    __shared__ float sx[512];
    size_t t = (size_t)b*SEQL + (SEQL-1);
    sx[h]     = g_v[t*512 + h];
    sx[h+256] = g_v[t*512 + 256 + h];
    __syncthreads();
    float acc = 0.f;
    #pragma unroll 8
    for (int k=0;k<512;k++) acc = fmaf(sx[k], Beff1[(size_t)h*512 + k], acc);
    g_x[t*HD + h] += acc + D1[h]*g_h[t*HD + h];
}
__device__ __forceinline__ float blk_sum256(float v){
    __shared__ float sm[8];
    int lane = threadIdx.x & 31, w = threadIdx.x >> 5;
    #pragma unroll
    for (int o=16;o;o>>=1) v += __shfl_xor_sync(0xffffffffu, v, o);
    if (lane == 0) sm[w] = v;
    __syncthreads();
    float r = (threadIdx.x < 8) ? sm[threadIdx.x] : 0.f;
    if (threadIdx.x < 32){
        #pragma unroll
        for (int o=4;o;o>>=1) r += __shfl_xor_sync(0xffffffffu, r, o);
    }
    if (threadIdx.x == 0) sm[0] = r;
    __syncthreads();
    float out = sm[0];
    __syncthreads();
    return out;
}
__global__ void fk_ln_last(const float* __restrict__ gg, const float* __restrict__ bb){
    int b = blockIdx.x, j = threadIdx.x;
    size_t t = (size_t)b*SEQL + (SEQL-1);
    float x = g_x[t*HD + j];
    float m = blk_sum256(x) * (1.0f/HD);
    float d = x - m;
    float var = blk_sum256(d*d) * (1.0f/HD);
    float r = rsqrtf(var + LNEPS);
    r = r * (1.5f - 0.5f*(var+LNEPS)*r*r);
    g_sa[b*HD + j] = d*r*gg[j] + bb[j];
}
__global__ void fk_mlp1(const float* __restrict__ W1b, const float* __restrict__ b1b){
    int b = blockIdx.x, j = threadIdx.x;
    __shared__ float sh[HD];
    sh[j] = g_sa[b*HD + j];
    __syncthreads();
    float acc = 0.f;
    #pragma unroll 8
    for (int h=0;h<HD;h++) acc = fmaf(sh[h], W1b[(size_t)h*HD + j], acc);
    g_sb[b*HD + j] = fmaxf(acc + b1b[j], 0.f);
}
__global__ void fk_mlp2_lnf(const float* __restrict__ W2b, const float* __restrict__ b2b,
                            const int* __restrict__ seqs,
                            const float* __restrict__ lfg, const float* __restrict__ lfb){
    int b = blockIdx.x, j = threadIdx.x;
    __shared__ float sh[HD];
    sh[j] = g_sb[b*HD + j];
    __syncthreads();
    float acc = 0.f;
    #pragma unroll 8
    for (int h=0;h<HD;h++) acc = fmaf(sh[h], W2b[(size_t)h*HD + j], acc);
    size_t t = (size_t)b*SEQL + (SEQL-1);
    float xv = g_x[t*HD + j] + acc + b2b[j];
    if (seqs[t] == 0) xv = 0.f;
    float m = blk_sum256(xv) * (1.0f/HD);
    float d = xv - m;
    float var = blk_sum256(d*d) * (1.0f/HD);
    float r = rsqrtf(var + LNEPS);
    r = r * (1.5f - 0.5f*(var+LNEPS)*r*r);
    g_sc[b*HD + j] = d*r*lfg[j] + lfb[j];
}
__global__ void fk_logits(const int* __restrict__ idxs, const float* __restrict__ emb,
                          float* __restrict__ out){
    int b = blockIdx.x, tid = threadIdx.x;
    int w = tid >> 5, lane = tid & 31;
    __shared__ __align__(16) float sh[HD];
    sh[tid] = g_sc[b*HD + tid];
    __syncthreads();
    const float4* sh4 = (const float4*)sh;
    float4 s0 = sh4[lane], s1 = sh4[lane+32];
    for (int c = w; c < 101; c += 8){
        int id = idxs[b*101 + c];
        const float4* e4 = (const float4*)(emb + (size_t)id*HD);
        float4 a0 = e4[lane], a1 = e4[lane+32];
        float p = a0.x*s0.x + a0.y*s0.y + a0.z*s0.z + a0.w*s0.w
                + a1.x*s1.x + a1.y*s1.y + a1.z*s1.z + a1.w*s1.w;
        #pragma unroll
        for (int o=16;o;o>>=1) p += __shfl_xor_sync(0xffffffffu, p, o);
        if (lane == 0) out[b*101 + c] = p;
    }
}

// ---------------- driver ----------------
extern "C" void kernel_launch(void* const* d_in, const int* in_sizes, int n_in,
                              void* d_out, int out_size){
    const int*   seqs = (const int*)  d_in[0];
    const int*   idxs = (const int*)  d_in[1];
    const float* emb  = (const float*)d_in[2];
    const float* pos  = (const float*)d_in[3];
    const float* ln_g = (const float*)d_in[4];
    const float* ln_b = (const float*)d_in[5];
    const float* lar  = (const float*)d_in[6];
    const float* aim  = (const float*)d_in[7];
    const float* Bssm = (const float*)d_in[8];
    const float* Cssm = (const float*)d_in[9];
    const float* Dssm = (const float*)d_in[10];
    const float* lstep= (const float*)d_in[11];
    const float* W1   = (const float*)d_in[12];
    const float* b1   = (const float*)d_in[13];
    const float* W2   = (const float*)d_in[14];
    const float* b2   = (const float*)d_in[15];
    const float* lfg  = (const float*)d_in[16];
    const float* lfb  = (const float*)d_in[17];
    float* out = (float*)d_out;

    float *p_x, *p_v, *p_h, *p_Bst, *p_Bef, *p_W1t, *p_W2t;
    __nv_bfloat16 *p_ahi, *p_alo;
    __nv_bfloat16 *p_bsth, *p_bstl, *p_befh, *p_befl, *p_w1h, *p_w1l, *p_w2h, *p_w2l;
    cudaGetSymbolAddress((void**)&p_x,   g_x);
    cudaGetSymbolAddress((void**)&p_h,   g_h);
    cudaGetSymbolAddress((void**)&p_v,   g_v);
    cudaGetSymbolAddress((void**)&p_Bst, g_Bstack);
    cudaGetSymbolAddress((void**)&p_Bef, g_Beff);
    cudaGetSymbolAddress((void**)&p_W1t, g_W1t);
    cudaGetSymbolAddress((void**)&p_W2t, g_W2t);
    cudaGetSymbolAddress((void**)&p_ahi, g_ahi);
    cudaGetSymbolAddress((void**)&p_alo, g_alo);
    cudaGetSymbolAddress((void**)&p_bsth,g_bst_h);
    cudaGetSymbolAddress((void**)&p_bstl,g_bst_l);
    cudaGetSymbolAddress((void**)&p_befh,g_bef_h);
    cudaGetSymbolAddress((void**)&p_befl,g_bef_l);
    cudaGetSymbolAddress((void**)&p_w1h, g_w1_h);
    cudaGetSymbolAddress((void**)&p_w1l, g_w1_l);
    cudaGetSymbolAddress((void**)&p_w2h, g_w2_h);
    cudaGetSymbolAddress((void**)&p_w2l, g_w2_l);
    // MLP intermediate hi/lo alias the (dead in that window) scan buffer
    __nv_bfloat16* p_mhi = (__nv_bfloat16*)p_v;
    __nv_bfloat16* p_mlo = (__nv_bfloat16*)p_v + (size_t)TTOT*256;

    cudaFuncSetAttribute(tcg<0>, cudaFuncAttributeMaxDynamicSharedMemorySize, GSMEM);
    cudaFuncSetAttribute(tcg<1>, cudaFuncAttributeMaxDynamicSharedMemorySize, GSMEM);
    cudaFuncSetAttribute(tcg<2>, cudaFuncAttributeMaxDynamicSharedMemorySize, GSMEM);
    cudaFuncSetAttribute(tcg<3>, cudaFuncAttributeMaxDynamicSharedMemorySize, GSMEM);

    prep_coef  <<<1, 256>>>(lar, aim, lstep);
    prep_bstack<<<dim3(512,2), 256>>>(Bssm);
    prep_beff  <<<dim3(256,2), 256>>>(Cssm);
    prep_wt    <<<dim3(256,2,2), 256>>>(W1, W2);
    split_f32<<<2*512*256/1024, 256>>>(p_Bst, p_bsth, p_bstl);
    split_f32<<<2*256*512/1024, 256>>>(p_Bef, p_befh, p_befl);
    split_f32<<<2*256*256/1024, 256>>>(p_W1t, p_w1h, p_w1l);
    split_f32<<<2*256*256/1024, 256>>>(p_W2t, p_w2h, p_w2l);

    embed_kernel<<<TTOT/4, 256>>>(seqs, emb, pos);

    // ---- block 0 ----
    ln_split<<<TTOT/8, 256>>>(ln_g, ln_b);
    tcg<0><<<dim3(4,1024), 256, GSMEM>>>(p_ahi, p_alo, p_bsth, p_bstl, p_v, 256, 512,
                                         nullptr, nullptr, nullptr, nullptr, nullptr);
    scan_kernel<<<dim3(BSZ,4), 64>>>(0);
    split_f32<<<(size_t)TTOT*512/1024, 256>>>(p_v, p_ahi, p_alo);
    tcg<1><<<dim3(2,1024), 256, GSMEM>>>(p_ahi, p_alo, p_befh, p_befl, p_x, 512, 256,
                                         Dssm, p_h, nullptr, nullptr, nullptr);
    ln_split<<<TTOT/8, 256>>>(ln_g, ln_b);
    tcg<2><<<dim3(2,1024), 256, GSMEM>>>(p_ahi, p_alo, p_w1h, p_w1l, nullptr, 256, 256,
                                         b1, nullptr, nullptr, p_mhi, p_mlo);
    tcg<3><<<dim3(2,1024), 256, GSMEM>>>(p_mhi, p_mlo, p_w2h, p_w2l, p_x, 256, 256,
                                         b2, nullptr, seqs, nullptr, nullptr);

    // ---- block 1 ----
    ln_split<<<TTOT/8, 256>>>(ln_g + HD, ln_b + HD);
    tcg<0><<<dim3(4,1024), 256, GSMEM>>>(p_ahi, p_alo, p_bsth + 512*256, p_bstl + 512*256,
                                         p_v, 256, 512, nullptr, nullptr, nullptr, nullptr, nullptr);
    scan_kernel<<<dim3(BSZ,4), 64>>>(1);
    fk_y1<<<BSZ, 256>>>(p_Bef + 256*512, Dssm + HD);

    // ---- last-token tail ----
    fk_ln_last<<<BSZ, 256>>>(ln_g + HD, ln_b + HD);
    fk_mlp1<<<BSZ, 256>>>(W1 + 65536, b1 + HD);
    fk_mlp2_lnf<<<BSZ, 256>>>(W2 + 65536, b2 + HD, seqs, lfg, lfb);
    fk_logits<<<BSZ, 256>>>(idxs, emb, out);
}